// round 5
// baseline (speedup 1.0000x reference)
#include <cuda_runtime.h>
#include <math.h>

typedef unsigned long long ull;

// ---------------------------------------------------------------------------
// packed fp32x2 helpers (Blackwell FFMA2)
// ---------------------------------------------------------------------------
#define FMA2(d, a, b, c) \
    asm("fma.rn.f32x2 %0, %1, %2, %3;" : "=l"(d) : "l"(a), "l"(b), "l"(c))

static __device__ __forceinline__ ull pack2(float lo, float hi) {
    ull r; asm("mov.b64 %0, {%1, %2};" : "=l"(r) : "f"(lo), "f"(hi)); return r;
}
static __device__ __forceinline__ float2 unpack2(ull v) {
    float2 r; asm("mov.b64 {%0, %1}, %2;" : "=f"(r.x), "=f"(r.y) : "l"(v)); return r;
}
static __device__ __forceinline__ ull lds64(const float* p) {
    return *reinterpret_cast<const ull*>(p);
}

// Scratch: per-image softmax probabilities (1024 batches * 16 digits * 10)
__device__ float g_probs[1024 * 16 * 10];

// ---------------------------------------------------------------------------
// shared memory layout (float offsets)
// ---------------------------------------------------------------------------
#define OFF_DW1T  0        // [120][258]  transposed dw1, padded
#define DW1_STR   258
#define OFF_DW2T  30960    // [84][122]   transposed dw2, padded
#define DW2_STR   122
#define OFF_DW3   41208    // 840
#define OFF_W1    42048    // 150 (+2)
#define OFF_W2    42200    // 2400
#define OFF_B1    44600    // 6 (+2)
#define OFF_B2    44608    // 16
#define OFF_DB1   44624    // 120
#define OFF_DB2   44744    // 84
#define OFF_DB3   44828    // 10 (+2)
#define OFF_Q     44840    // per-quarter blocks
#define Q_STRIDE  2992
// within a quarter:
#define Q_IMG     0        // 784
#define Q_P1T     784      // [6][12][24]  pooled conv1, dup pairs
#define Q_P2      2512     // 256 (+8 pad -> 264)
#define Q_FC1     2776     // 120
#define Q_FC2     2896     // 84
#define Q_LOG     2980     // 10 (+2)
#define SMEM_FLOATS (OFF_Q + 4 * Q_STRIDE)   // 56808 floats = 227,232 B

#define QBAR() asm volatile("bar.sync %0, 128;" :: "r"(q + 1) : "memory")

// ---------------------------------------------------------------------------
// Kernel 1: persistent fused LeNet. 148 CTAs x 512 threads; 4 independent
// 128-thread quarters, one image in flight each (phases overlap across
// quarters -> all SMSPs stay fed with FMA work).
// ---------------------------------------------------------------------------
__global__ void __launch_bounds__(512, 1) cnn_kernel(
    const float* __restrict__ inputs,
    const float* __restrict__ cw1, const float* __restrict__ cb1,
    const float* __restrict__ cw2, const float* __restrict__ cb2,
    const float* __restrict__ dw1, const float* __restrict__ db1,
    const float* __restrict__ dw2, const float* __restrict__ db2,
    const float* __restrict__ dw3, const float* __restrict__ db3,
    int nimg)
{
    extern __shared__ float sm[];
    const int tid = threadIdx.x;

    // ---- one-time weight staging ----
    for (int idx = tid; idx < 256 * 120; idx += 512) {
        int k = idx / 120, j = idx % 120;               // dw1[k][j]
        sm[OFF_DW1T + j * DW1_STR + k] = dw1[idx];
    }
    for (int idx = tid; idx < 120 * 84; idx += 512) {
        int k = idx / 84, j = idx % 84;                 // dw2[k][j]
        sm[OFF_DW2T + j * DW2_STR + k] = dw2[idx];
    }
    for (int idx = tid; idx < 840;  idx += 512) sm[OFF_DW3 + idx] = dw3[idx];
    for (int idx = tid; idx < 150;  idx += 512) sm[OFF_W1  + idx] = cw1[idx];
    for (int idx = tid; idx < 2400; idx += 512) sm[OFF_W2  + idx] = cw2[idx];
    if (tid < 6)   sm[OFF_B1  + tid] = cb1[tid];
    if (tid < 16)  sm[OFF_B2  + tid] = cb2[tid];
    if (tid < 120) sm[OFF_DB1 + tid] = db1[tid];
    if (tid < 84)  sm[OFF_DB2 + tid] = db2[tid];
    if (tid < 10)  sm[OFF_DB3 + tid] = db3[tid];
    __syncthreads();

    const int q  = tid >> 7;                 // quarter 0..3
    const int t  = tid & 127;                // thread within quarter
    const int rt = (t + (q << 5)) & 127;     // rotated role (SMSP balance)

    float* sq_img = sm + OFF_Q + q * Q_STRIDE + Q_IMG;
    float* sq_p1t = sm + OFF_Q + q * Q_STRIDE + Q_P1T;
    float* sq_p2  = sm + OFF_Q + q * Q_STRIDE + Q_P2;
    float* sq_fc1 = sm + OFF_Q + q * Q_STRIDE + Q_FC1;
    float* sq_fc2 = sm + OFF_Q + q * Q_STRIDE + Q_FC2;
    float* sq_log = sm + OFF_Q + q * Q_STRIDE + Q_LOG;

    const int qstep = gridDim.x * 4;

    // ---- prologue: each quarter loads its first image ----
    {
        const int img0 = blockIdx.x * 4 + q;
        if (img0 < nimg) {
            const float4* iv = reinterpret_cast<const float4*>(inputs + (size_t)img0 * 784);
            float4* ov = reinterpret_cast<float4*>(sq_img);
            for (int i = t; i < 196; i += 128) ov[i] = iv[i];
        }
    }
    QBAR();

    for (int img = blockIdx.x * 4 + q; img < nimg; img += qstep) {

        // ====== conv1 (5x5->6) + relu + pool. roles 0..71 ======
        if (rt < 72) {
            const int py = rt / 6, xg = rt % 6, x0 = 4 * xg;
            ull bp[3];
            #pragma unroll
            for (int cp = 0; cp < 3; cp++)
                bp[cp] = pack2(sm[OFF_B1 + 2 * cp], sm[OFF_B1 + 2 * cp + 1]);
            ull acc[2][4][3];
            #pragma unroll
            for (int dy = 0; dy < 2; dy++)
                #pragma unroll
                for (int dx = 0; dx < 4; dx++)
                    #pragma unroll
                    for (int cp = 0; cp < 3; cp++) acc[dy][dx][cp] = bp[cp];

            for (int r = 0; r < 6; r++) {
                const int iy = 2 * py + r;
                const float4* row = reinterpret_cast<const float4*>(sq_img + iy * 28 + x0);
                float4 v0 = row[0], v1 = row[1];
                ull ap[8];
                ap[0] = pack2(v0.x, v0.x); ap[1] = pack2(v0.y, v0.y);
                ap[2] = pack2(v0.z, v0.z); ap[3] = pack2(v0.w, v0.w);
                ap[4] = pack2(v1.x, v1.x); ap[5] = pack2(v1.y, v1.y);
                ap[6] = pack2(v1.z, v1.z); ap[7] = pack2(v1.w, v1.w);
                #pragma unroll
                for (int dy = 0; dy < 2; dy++) {
                    const int ky = r - dy;
                    if (ky < 0 || ky > 4) continue;
                    #pragma unroll
                    for (int kx = 0; kx < 5; kx++) {
                        const float* wp = sm + OFF_W1 + (ky * 5 + kx) * 6;
                        #pragma unroll
                        for (int cp = 0; cp < 3; cp++) {
                            ull w = lds64(wp + 2 * cp);
                            #pragma unroll
                            for (int dx = 0; dx < 4; dx++)
                                FMA2(acc[dy][dx][cp], ap[kx + dx], w, acc[dy][dx][cp]);
                        }
                    }
                }
            }
            #pragma unroll
            for (int cp = 0; cp < 3; cp++) {
                #pragma unroll
                for (int dxp = 0; dxp < 2; dxp++) {
                    float2 a0 = unpack2(acc[0][2 * dxp][cp]);
                    float2 a1 = unpack2(acc[0][2 * dxp + 1][cp]);
                    float2 b0 = unpack2(acc[1][2 * dxp][cp]);
                    float2 b1 = unpack2(acc[1][2 * dxp + 1][cp]);
                    float m0 = fmaxf(fmaxf(fmaxf(a0.x, a1.x), fmaxf(b0.x, b1.x)), 0.0f);
                    float m1 = fmaxf(fmaxf(fmaxf(a0.y, a1.y), fmaxf(b0.y, b1.y)), 0.0f);
                    const int px = 2 * xg + dxp;
                    *reinterpret_cast<ull*>(sq_p1t + ((2 * cp)     * 12 + py) * 24 + 2 * px) = pack2(m0, m0);
                    *reinterpret_cast<ull*>(sq_p1t + ((2 * cp + 1) * 12 + py) * 24 + 2 * px) = pack2(m1, m1);
                }
            }
        }
        QBAR();

        // ====== conv2 (5x5x6->16) + relu + pool. ALL 128 threads ======
        // role = (py 0..3, xg 0..3, cg 0..7): conv rows 2py..2py+1,
        // conv cols 2xg..2xg+1, channels 2cg..2cg+1. One pooled output.
        {
            const int py = rt >> 5;
            const int xg = (rt >> 3) & 3;
            const int cg = rt & 7;
            const int x0 = 2 * xg;

            ull bp = lds64(sm + OFF_B2 + 2 * cg);
            ull acc[2][2];
            acc[0][0] = bp; acc[0][1] = bp; acc[1][0] = bp; acc[1][1] = bp;

            for (int r = 0; r < 6; r++) {
                const int iy = 2 * py + r;
                for (int i = 0; i < 6; i++) {
                    const float* row = sq_p1t + (i * 12 + iy) * 24 + 2 * x0;
                    ull ap[6];
                    #pragma unroll
                    for (int j = 0; j < 6; j++) ap[j] = lds64(row + 2 * j);
                    #pragma unroll
                    for (int dy = 0; dy < 2; dy++) {
                        const int ky = r - dy;
                        if (ky < 0 || ky > 4) continue;
                        #pragma unroll
                        for (int kx = 0; kx < 5; kx++) {
                            ull w = lds64(sm + OFF_W2 + ((ky * 5 + kx) * 6 + i) * 16 + 2 * cg);
                            FMA2(acc[dy][0], ap[kx],     w, acc[dy][0]);
                            FMA2(acc[dy][1], ap[kx + 1], w, acc[dy][1]);
                        }
                    }
                }
            }
            float2 a0 = unpack2(acc[0][0]);
            float2 a1 = unpack2(acc[0][1]);
            float2 b0 = unpack2(acc[1][0]);
            float2 b1 = unpack2(acc[1][1]);
            float m0 = fmaxf(fmaxf(fmaxf(a0.x, a1.x), fmaxf(b0.x, b1.x)), 0.0f);
            float m1 = fmaxf(fmaxf(fmaxf(a0.y, a1.y), fmaxf(b0.y, b1.y)), 0.0f);
            *reinterpret_cast<ull*>(sq_p2 + (py * 4 + xg) * 16 + 2 * cg) = pack2(m0, m1);
        }
        QBAR();

        // ====== fc1: 256 -> 120, relu. roles 0..119 ======
        if (rt < 120) {
            const float* wr = sm + OFF_DW1T + rt * DW1_STR;
            ull acc0 = pack2(0.0f, 0.0f), acc1 = pack2(0.0f, 0.0f);
            #pragma unroll 8
            for (int k = 0; k < 256; k += 4) {
                ull a0 = lds64(sq_p2 + k), a1 = lds64(sq_p2 + k + 2);
                ull w0 = lds64(wr + k),    w1 = lds64(wr + k + 2);
                FMA2(acc0, a0, w0, acc0);
                FMA2(acc1, a1, w1, acc1);
            }
            float2 s0 = unpack2(acc0), s1 = unpack2(acc1);
            float v = s0.x + s0.y + s1.x + s1.y + sm[OFF_DB1 + rt];
            sq_fc1[rt] = fmaxf(v, 0.0f);
        }
        QBAR();

        // ====== fc2: 120 -> 84, relu. roles 0..83 ======
        if (rt < 84) {
            const float* wr = sm + OFF_DW2T + rt * DW2_STR;
            ull acc0 = pack2(0.0f, 0.0f), acc1 = pack2(0.0f, 0.0f);
            #pragma unroll 6
            for (int k = 0; k < 120; k += 4) {
                ull a0 = lds64(sq_fc1 + k), a1 = lds64(sq_fc1 + k + 2);
                ull w0 = lds64(wr + k),     w1 = lds64(wr + k + 2);
                FMA2(acc0, a0, w0, acc0);
                FMA2(acc1, a1, w1, acc1);
            }
            float2 s0 = unpack2(acc0), s1 = unpack2(acc1);
            float v = s0.x + s0.y + s1.x + s1.y + sm[OFF_DB2 + rt];
            sq_fc2[rt] = fmaxf(v, 0.0f);
        }
        QBAR();

        // ====== fc3: 84 -> 10. roles 0..9 ======
        if (rt < 10) {
            float acc = sm[OFF_DB3 + rt];
            #pragma unroll 4
            for (int k = 0; k < 84; k++)
                acc = fmaf(sq_fc2[k], sm[OFF_DW3 + k * 10 + rt], acc);
            sq_log[rt] = acc;
        }
        QBAR();

        // ====== softmax (role 0) + prefetch next image (threads t) ======
        {
            const int nb = img + qstep;
            if (nb < nimg && t < 98) {
                const float4* iv = reinterpret_cast<const float4*>(inputs + (size_t)nb * 784);
                float4* ov = reinterpret_cast<float4*>(sq_img);
                ov[t]      = iv[t];
                ov[t + 98] = iv[t + 98];
            }
            if (rt == 0) {
                float mx = sq_log[0];
                #pragma unroll
                for (int j = 1; j < 10; j++) mx = fmaxf(mx, sq_log[j]);
                float e[10], s = 0.0f;
                #pragma unroll
                for (int j = 0; j < 10; j++) { e[j] = __expf(sq_log[j] - mx); s += e[j]; }
                float inv = 1.0f / s;
                float* po = g_probs + (size_t)img * 10;
                #pragma unroll
                for (int j = 0; j < 10; j++) po[j] = e[j] * inv;
            }
        }
        QBAR();
    }
}

// ---------------------------------------------------------------------------
// Kernel 2: Luhn DP. 64 threads/block, probs staged through smem
// (stride 161 -> conflict-free), DP fully register-resident.
// ---------------------------------------------------------------------------
static __device__ __forceinline__ float luhn16_from(const float* __restrict__ p)
{
    const int LUHN[10] = {0, 5, 1, 6, 2, 7, 3, 8, 4, 9};
    const int m = 15;
    float cur[10];
    #pragma unroll
    for (int j = 0; j < 10; j++)
        cur[j] = ((0 % 2) == (m % 2)) ? p[10 + LUHN[j]] : p[10 + j];
    #pragma unroll
    for (int i = 1; i < m; i++) {
        float dd[10];
        #pragma unroll
        for (int j = 0; j < 10; j++)
            dd[j] = ((i % 2) == (m % 2)) ? p[(i + 1) * 10 + LUHN[j]] : p[(i + 1) * 10 + j];
        float nxt[10];
        #pragma unroll
        for (int s = 0; s < 10; s++) nxt[s] = 0.0f;
        #pragma unroll
        for (int a = 0; a < 10; a++)
            #pragma unroll
            for (int qd = 0; qd < 10; qd++)
                nxt[(a + qd) % 10] = fmaf(cur[a], dd[qd], nxt[(a + qd) % 10]);
        #pragma unroll
        for (int s = 0; s < 10; s++) cur[s] = nxt[s];
    }
    float t10 = 0.0f;
    #pragma unroll
    for (int a = 1; a < 10; a++) t10 = fmaf(p[a], cur[10 - a], t10);
    return logf(t10);
}

__device__ float luhn_generic(const float* __restrict__ p, int n)
{
    const int LUHN[10] = {0, 5, 1, 6, 2, 7, 3, 8, 4, 9};
    const int m = n - 1;
    float cur[10];
    {
        const float* d = p + 10;
        bool perm = ((0 & 1) == (m & 1));
        #pragma unroll
        for (int j = 0; j < 10; j++) cur[j] = perm ? d[LUHN[j]] : d[j];
    }
    for (int i = 1; i < m; i++) {
        const float* d = p + (size_t)(i + 1) * 10;
        bool perm = ((i & 1) == (m & 1));
        float dd[10];
        #pragma unroll
        for (int j = 0; j < 10; j++) dd[j] = perm ? d[LUHN[j]] : d[j];
        float nxt[10];
        #pragma unroll
        for (int s = 0; s < 10; s++) nxt[s] = 0.0f;
        #pragma unroll
        for (int a = 0; a < 10; a++)
            #pragma unroll
            for (int qd = 0; qd < 10; qd++)
                nxt[(a + qd) % 10] = fmaf(cur[a], dd[qd], nxt[(a + qd) % 10]);
        #pragma unroll
        for (int s = 0; s < 10; s++) cur[s] = nxt[s];
    }
    float t10 = 0.0f;
    #pragma unroll
    for (int a = 1; a < 10; a++) t10 = fmaf(p[a], cur[10 - a], t10);
    return logf(t10);
}

__global__ void luhn_kernel(float* __restrict__ out, int B, int n)
{
    if (n == 16) {
        __shared__ float sp[64 * 161];
        const int tid = threadIdx.x;
        const int b0  = blockIdx.x * 64;
        const int nb  = (B - b0 < 64) ? (B - b0) : 64;
        const float4* src = reinterpret_cast<const float4*>(g_probs + (size_t)b0 * 160);
        const int tot4 = nb * 40;
        for (int i = tid; i < tot4; i += 64) {
            float4 v = src[i];
            const int bb = i / 40, w = i % 40;
            float* d = sp + bb * 161 + w * 4;
            d[0] = v.x; d[1] = v.y; d[2] = v.z; d[3] = v.w;
        }
        __syncthreads();
        const int b = b0 + tid;
        if (b < B) out[b] = luhn16_from(sp + tid * 161);
    } else {
        int b = blockIdx.x * blockDim.x + threadIdx.x;
        if (b < B) out[b] = luhn_generic(g_probs + (size_t)b * n * 10, n);
    }
}

// ---------------------------------------------------------------------------
extern "C" void kernel_launch(void* const* d_in, const int* in_sizes, int n_in,
                              void* d_out, int out_size)
{
    const float* inputs = (const float*)d_in[0];
    const float* cw1    = (const float*)d_in[1];
    const float* cb1    = (const float*)d_in[2];
    const float* cw2    = (const float*)d_in[3];
    const float* cb2    = (const float*)d_in[4];
    const float* dw1    = (const float*)d_in[5];
    const float* db1    = (const float*)d_in[6];
    const float* dw2    = (const float*)d_in[7];
    const float* db2    = (const float*)d_in[8];
    const float* dw3    = (const float*)d_in[9];
    const float* db3    = (const float*)d_in[10];
    float* out = (float*)d_out;

    const int B = out_size;                      // 1024
    const int n = in_sizes[0] / (B * 784);       // 16
    const int nimg = B * n;

    const size_t smem_bytes = SMEM_FLOATS * sizeof(float);  // 227,232 B
    cudaFuncSetAttribute(cnn_kernel, cudaFuncAttributeMaxDynamicSharedMemorySize,
                         (int)smem_bytes);

    cnn_kernel<<<148, 512, smem_bytes>>>(inputs, cw1, cb1, cw2, cb2,
                                         dw1, db1, dw2, db2, dw3, db3, nimg);
    luhn_kernel<<<(B + 63) / 64, 64>>>(out, B, n);
}

// round 6
// speedup vs baseline: 1.2990x; 1.2990x over previous
#include <cuda_runtime.h>
#include <math.h>

typedef unsigned long long ull;

// ---------------------------------------------------------------------------
// packed fp32x2 helpers (Blackwell FFMA2)
// ---------------------------------------------------------------------------
#define FMA2(d, a, b, c) \
    asm("fma.rn.f32x2 %0, %1, %2, %3;" : "=l"(d) : "l"(a), "l"(b), "l"(c))

static __device__ __forceinline__ ull pack2(float lo, float hi) {
    ull r; asm("mov.b64 %0, {%1, %2};" : "=l"(r) : "f"(lo), "f"(hi)); return r;
}
static __device__ __forceinline__ float2 unpack2(ull v) {
    float2 r; asm("mov.b64 {%0, %1}, %2;" : "=f"(r.x), "=f"(r.y) : "l"(v)); return r;
}
static __device__ __forceinline__ ull lds64(const float* p) {
    return *reinterpret_cast<const ull*>(p);
}

// Scratch: per-image softmax probabilities (1024 batches * 16 digits * 10)
__device__ float g_probs[1024 * 16 * 10];

// ---------------------------------------------------------------------------
// shared memory layout (float offsets)
// ---------------------------------------------------------------------------
#define OFF_DW1T  0        // [120][260]  transposed dw1, 16B-aligned rows
#define DW1_STR   260
#define OFF_DW2T  31200    // [84][124]   transposed dw2, 16B-aligned rows
#define DW2_STR   124
#define OFF_DW3   41616    // 840
#define OFF_W1P   42456    // [25][8]  conv1 weights, 6 ch + 2 pad per tap
#define OFF_W2X   42656    // 2400: [(pk*3+ip)][32] = [cg-pair 0..7][i0pair,i1pair]
#define OFF_B1    45056    // 8
#define OFF_B2    45064    // 16
#define OFF_DB1   45080    // 120
#define OFF_DB2   45200    // 88
#define OFF_DB3   45288    // 12
#define OFF_IMG   45300    // [4][784]
#define OFF_P1T   48436    // [4][6][12][24]  pooled conv1, dup pairs
#define P1_IMG_STR 1728
#define OFF_P2    55348    // [4][264]
#define P2_STR    264
#define OFF_FC1   56404    // [4][120]
#define OFF_FC2   56884    // [4][88]
#define OFF_LOG   57236    // [4][12]
#define SMEM_FLOATS 57284  // = 229,136 bytes

// ---------------------------------------------------------------------------
// Kernel 1: persistent fused LeNet. 148 CTAs x 512 threads, CTA-wide phases
// over batches of 4 images. All conv loops fully unrolled, 128-bit LDS.
// ---------------------------------------------------------------------------
__global__ void __launch_bounds__(512, 1) cnn_kernel(
    const float* __restrict__ inputs,
    const float* __restrict__ cw1, const float* __restrict__ cb1,
    const float* __restrict__ cw2, const float* __restrict__ cb2,
    const float* __restrict__ dw1, const float* __restrict__ db1,
    const float* __restrict__ dw2, const float* __restrict__ db2,
    const float* __restrict__ dw3, const float* __restrict__ db3,
    int nimg)
{
    extern __shared__ float sm[];
    const int tid = threadIdx.x;

    // ---- one-time weight staging ----
    for (int idx = tid; idx < 256 * 120; idx += 512) {
        int k = idx / 120, j = idx % 120;               // dw1[k][j]
        sm[OFF_DW1T + j * DW1_STR + k] = dw1[idx];
    }
    for (int idx = tid; idx < 120 * 84; idx += 512) {
        int k = idx / 84, j = idx % 84;                 // dw2[k][j]
        sm[OFF_DW2T + j * DW2_STR + k] = dw2[idx];
    }
    for (int idx = tid; idx < 840; idx += 512) sm[OFF_DW3 + idx] = dw3[idx];
    for (int idx = tid; idx < 150; idx += 512) {        // w1p: [pk][8]
        int pk = idx / 6, c = idx % 6;
        sm[OFF_W1P + pk * 8 + c] = cw1[idx];
    }
    for (int idx = tid; idx < 2400; idx += 512) {       // w2x interleaved
        int p = idx >> 4, ch = idx & 15;
        int pk = p / 6, i = p % 6;
        sm[OFF_W2X + (pk * 3 + (i >> 1)) * 32 + (ch >> 1) * 4 + (i & 1) * 2 + (ch & 1)]
            = cw2[idx];
    }
    if (tid < 6)   sm[OFF_B1  + tid] = cb1[tid];
    if (tid < 16)  sm[OFF_B2  + tid] = cb2[tid];
    if (tid < 120) sm[OFF_DB1 + tid] = db1[tid];
    if (tid < 84)  sm[OFF_DB2 + tid] = db2[tid];
    if (tid < 10)  sm[OFF_DB3 + tid] = db3[tid];

    // ---- prologue: load first batch of 4 images ----
    {
        const int b0 = blockIdx.x * 4;
        if (b0 < nimg) {
            const float4* iv = reinterpret_cast<const float4*>(inputs + (size_t)b0 * 784);
            float4* ov = reinterpret_cast<float4*>(sm + OFF_IMG);
            for (int i = tid; i < 784; i += 512) ov[i] = iv[i];
        }
    }
    __syncthreads();

    for (int base = blockIdx.x * 4; base < nimg; base += gridDim.x * 4) {

        // =========== conv1 (5x5->6) + relu + pool. 288 threads ===========
        if (tid < 288) {
            const int img = tid / 72;
            const int r72 = tid % 72;
            const int py = r72 / 6, xg = r72 % 6, x0 = 4 * xg;
            const float* ibase = sm + OFF_IMG + img * 784 + 2 * py * 28 + x0;
            float* s_p1 = sm + OFF_P1T + img * P1_IMG_STR;

            ull bp[3];
            #pragma unroll
            for (int cp = 0; cp < 3; cp++)
                bp[cp] = pack2(sm[OFF_B1 + 2 * cp], sm[OFF_B1 + 2 * cp + 1]);
            ull acc[2][4][3];
            #pragma unroll
            for (int dy = 0; dy < 2; dy++)
                #pragma unroll
                for (int dx = 0; dx < 4; dx++)
                    #pragma unroll
                    for (int cp = 0; cp < 3; cp++) acc[dy][dx][cp] = bp[cp];

            #pragma unroll
            for (int r = 0; r < 6; r++) {
                float4 v0 = *reinterpret_cast<const float4*>(ibase + r * 28);
                float4 v1 = *reinterpret_cast<const float4*>(ibase + r * 28 + 4);
                ull ap[8];
                ap[0] = pack2(v0.x, v0.x); ap[1] = pack2(v0.y, v0.y);
                ap[2] = pack2(v0.z, v0.z); ap[3] = pack2(v0.w, v0.w);
                ap[4] = pack2(v1.x, v1.x); ap[5] = pack2(v1.y, v1.y);
                ap[6] = pack2(v1.z, v1.z); ap[7] = pack2(v1.w, v1.w);
                #pragma unroll
                for (int dy = 0; dy < 2; dy++) {
                    const int ky = r - dy;
                    if (ky < 0 || ky > 4) continue;
                    #pragma unroll
                    for (int kx = 0; kx < 5; kx++) {
                        const float* wp = sm + OFF_W1P + (ky * 5 + kx) * 8;
                        ulonglong2 w01 = *reinterpret_cast<const ulonglong2*>(wp);
                        ull w2 = lds64(wp + 4);
                        #pragma unroll
                        for (int dx = 0; dx < 4; dx++) {
                            FMA2(acc[dy][dx][0], ap[kx + dx], w01.x, acc[dy][dx][0]);
                            FMA2(acc[dy][dx][1], ap[kx + dx], w01.y, acc[dy][dx][1]);
                            FMA2(acc[dy][dx][2], ap[kx + dx], w2,    acc[dy][dx][2]);
                        }
                    }
                }
            }
            #pragma unroll
            for (int cp = 0; cp < 3; cp++) {
                #pragma unroll
                for (int dxp = 0; dxp < 2; dxp++) {
                    float2 a0 = unpack2(acc[0][2 * dxp][cp]);
                    float2 a1 = unpack2(acc[0][2 * dxp + 1][cp]);
                    float2 b0 = unpack2(acc[1][2 * dxp][cp]);
                    float2 b1 = unpack2(acc[1][2 * dxp + 1][cp]);
                    float m0 = fmaxf(fmaxf(fmaxf(a0.x, a1.x), fmaxf(b0.x, b1.x)), 0.0f);
                    float m1 = fmaxf(fmaxf(fmaxf(a0.y, a1.y), fmaxf(b0.y, b1.y)), 0.0f);
                    const int px = 2 * xg + dxp;
                    *reinterpret_cast<ull*>(s_p1 + ((2 * cp)     * 12 + py) * 24 + 2 * px) = pack2(m0, m0);
                    *reinterpret_cast<ull*>(s_p1 + ((2 * cp + 1) * 12 + py) * 24 + 2 * px) = pack2(m1, m1);
                }
            }
        }
        __syncthreads();

        // =========== conv2 (5x5x6->16) + relu + pool. 256 threads =========
        // thread = (img, py 0..3, xg 0..1, cg 0..7); fully unrolled; weight
        // LDS.128 feeds two input channels at once.
        if (tid < 256) {
            const int img = tid >> 6;
            const int u   = tid & 63;
            const int py = u >> 4, xg = (u >> 3) & 1, cg = u & 7;
            const int x0 = 4 * xg;
            const float* base0 = sm + OFF_P1T + img * P1_IMG_STR + 2 * py * 24 + 2 * x0;
            const float* wbase = sm + OFF_W2X + cg * 4;

            ull bp = lds64(sm + OFF_B2 + 2 * cg);
            ull acc[2][4];
            #pragma unroll
            for (int dy = 0; dy < 2; dy++)
                #pragma unroll
                for (int dx = 0; dx < 4; dx++) acc[dy][dx] = bp;

            #pragma unroll
            for (int r = 0; r < 6; r++) {
                #pragma unroll
                for (int ip = 0; ip < 3; ip++) {
                    const float* r0 = base0 + (2 * ip) * 288 + r * 24;
                    const float* r1 = r0 + 288;
                    ulonglong2 a00 = *reinterpret_cast<const ulonglong2*>(r0);
                    ulonglong2 a01 = *reinterpret_cast<const ulonglong2*>(r0 + 4);
                    ulonglong2 a02 = *reinterpret_cast<const ulonglong2*>(r0 + 8);
                    ulonglong2 a03 = *reinterpret_cast<const ulonglong2*>(r0 + 12);
                    ulonglong2 a10 = *reinterpret_cast<const ulonglong2*>(r1);
                    ulonglong2 a11 = *reinterpret_cast<const ulonglong2*>(r1 + 4);
                    ulonglong2 a12 = *reinterpret_cast<const ulonglong2*>(r1 + 8);
                    ulonglong2 a13 = *reinterpret_cast<const ulonglong2*>(r1 + 12);
                    ull ap0[8] = {a00.x, a00.y, a01.x, a01.y, a02.x, a02.y, a03.x, a03.y};
                    ull ap1[8] = {a10.x, a10.y, a11.x, a11.y, a12.x, a12.y, a13.x, a13.y};
                    #pragma unroll
                    for (int dy = 0; dy < 2; dy++) {
                        const int ky = r - dy;
                        if (ky < 0 || ky > 4) continue;
                        #pragma unroll
                        for (int kx = 0; kx < 5; kx++) {
                            ulonglong2 w = *reinterpret_cast<const ulonglong2*>(
                                wbase + ((ky * 5 + kx) * 3 + ip) * 32);
                            #pragma unroll
                            for (int dx = 0; dx < 4; dx++) {
                                FMA2(acc[dy][dx], ap0[kx + dx], w.x, acc[dy][dx]);
                                FMA2(acc[dy][dx], ap1[kx + dx], w.y, acc[dy][dx]);
                            }
                        }
                    }
                }
            }
            float* s_p2 = sm + OFF_P2 + img * P2_STR;
            #pragma unroll
            for (int dxp = 0; dxp < 2; dxp++) {
                float2 a0 = unpack2(acc[0][2 * dxp]);
                float2 a1 = unpack2(acc[0][2 * dxp + 1]);
                float2 b0 = unpack2(acc[1][2 * dxp]);
                float2 b1 = unpack2(acc[1][2 * dxp + 1]);
                float m0 = fmaxf(fmaxf(fmaxf(a0.x, a1.x), fmaxf(b0.x, b1.x)), 0.0f);
                float m1 = fmaxf(fmaxf(fmaxf(a0.y, a1.y), fmaxf(b0.y, b1.y)), 0.0f);
                const int px = 2 * xg + dxp;
                *reinterpret_cast<ull*>(s_p2 + (py * 4 + px) * 16 + 2 * cg) = pack2(m0, m1);
            }
        } else {
            // prefetch next batch of 4 images (img smem dead after conv1)
            const int nb = base + gridDim.x * 4;
            if (nb < nimg) {
                const float4* iv = reinterpret_cast<const float4*>(inputs + (size_t)nb * 784);
                float4* ov = reinterpret_cast<float4*>(sm + OFF_IMG);
                for (int i = tid - 256; i < 784; i += 256) ov[i] = iv[i];
            }
        }
        __syncthreads();

        // =========== fc1: 256 -> 120, relu. 480 threads (j*4+img) =========
        if (tid < 480) {
            const int j = tid >> 2, img = tid & 3;
            const float* act = sm + OFF_P2 + img * P2_STR;
            const float* wr  = sm + OFF_DW1T + j * DW1_STR;
            ull acc0 = pack2(0.0f, 0.0f), acc1 = pack2(0.0f, 0.0f);
            #pragma unroll 8
            for (int k = 0; k < 256; k += 4) {
                ulonglong2 av = *reinterpret_cast<const ulonglong2*>(act + k);
                ulonglong2 wv = *reinterpret_cast<const ulonglong2*>(wr + k);
                FMA2(acc0, av.x, wv.x, acc0);
                FMA2(acc1, av.y, wv.y, acc1);
            }
            float2 s0 = unpack2(acc0), s1 = unpack2(acc1);
            float v = s0.x + s0.y + s1.x + s1.y + sm[OFF_DB1 + j];
            sm[OFF_FC1 + img * 120 + j] = fmaxf(v, 0.0f);
        }
        __syncthreads();

        // =========== fc2: 120 -> 84, relu. 336 threads ===========
        if (tid < 336) {
            const int j = tid >> 2, img = tid & 3;
            const float* act = sm + OFF_FC1 + img * 120;
            const float* wr  = sm + OFF_DW2T + j * DW2_STR;
            ull acc0 = pack2(0.0f, 0.0f), acc1 = pack2(0.0f, 0.0f);
            #pragma unroll 6
            for (int k = 0; k < 120; k += 4) {
                ulonglong2 av = *reinterpret_cast<const ulonglong2*>(act + k);
                ulonglong2 wv = *reinterpret_cast<const ulonglong2*>(wr + k);
                FMA2(acc0, av.x, wv.x, acc0);
                FMA2(acc1, av.y, wv.y, acc1);
            }
            float2 s0 = unpack2(acc0), s1 = unpack2(acc1);
            float v = s0.x + s0.y + s1.x + s1.y + sm[OFF_DB2 + j];
            sm[OFF_FC2 + img * 88 + j] = fmaxf(v, 0.0f);
        }
        __syncthreads();

        // =========== fc3: 84 -> 10. 40 threads ===========
        if (tid < 40) {
            const int j = tid >> 2, img = tid & 3;
            const float* act = sm + OFF_FC2 + img * 88;
            float acc = sm[OFF_DB3 + j];
            #pragma unroll 4
            for (int k = 0; k < 84; k++)
                acc = fmaf(act[k], sm[OFF_DW3 + k * 10 + j], acc);
            sm[OFF_LOG + img * 12 + j] = acc;
        }
        __syncthreads();

        // =========== softmax -> scratch. 4 threads ===========
        if (tid < 4 && base + tid < nimg) {
            const float* lg = sm + OFF_LOG + tid * 12;
            float mx = lg[0];
            #pragma unroll
            for (int j = 1; j < 10; j++) mx = fmaxf(mx, lg[j]);
            float e[10], s = 0.0f;
            #pragma unroll
            for (int j = 0; j < 10; j++) { e[j] = __expf(lg[j] - mx); s += e[j]; }
            float inv = 1.0f / s;
            float* po = g_probs + (size_t)(base + tid) * 10;
            #pragma unroll
            for (int j = 0; j < 10; j++) po[j] = e[j] * inv;
        }
        __syncthreads();
    }
}

// ---------------------------------------------------------------------------
// Kernel 2: Luhn DP (round-3 variant: register-resident, high-MLP loads).
// ---------------------------------------------------------------------------
template <int N>
__device__ __forceinline__ float luhn_eval(const float* __restrict__ p)
{
    const int LUHN[10] = {0, 5, 1, 6, 2, 7, 3, 8, 4, 9};
    float4 v[(N * 10) / 4];
    const float4* pv = reinterpret_cast<const float4*>(p);
    #pragma unroll
    for (int i = 0; i < (N * 10) / 4; i++) v[i] = pv[i];
    float d[N * 10];
    #pragma unroll
    for (int i = 0; i < (N * 10) / 4; i++) {
        d[4 * i] = v[i].x; d[4 * i + 1] = v[i].y;
        d[4 * i + 2] = v[i].z; d[4 * i + 3] = v[i].w;
    }
    const int m = N - 1;
    float cur[10];
    #pragma unroll
    for (int j = 0; j < 10; j++)
        cur[j] = ((0 % 2) == (m % 2)) ? d[10 + LUHN[j]] : d[10 + j];
    #pragma unroll
    for (int i = 1; i < m; i++) {
        float dd[10];
        #pragma unroll
        for (int j = 0; j < 10; j++)
            dd[j] = ((i % 2) == (m % 2)) ? d[(i + 1) * 10 + LUHN[j]] : d[(i + 1) * 10 + j];
        float nxt[10];
        #pragma unroll
        for (int s = 0; s < 10; s++) nxt[s] = 0.0f;
        #pragma unroll
        for (int a = 0; a < 10; a++)
            #pragma unroll
            for (int q = 0; q < 10; q++)
                nxt[(a + q) % 10] = fmaf(cur[a], dd[q], nxt[(a + q) % 10]);
        #pragma unroll
        for (int s = 0; s < 10; s++) cur[s] = nxt[s];
    }
    float t10 = 0.0f;
    #pragma unroll
    for (int a = 1; a < 10; a++) t10 = fmaf(d[a], cur[10 - a], t10);
    return logf(t10);
}

__device__ float luhn_generic(const float* __restrict__ p, int n)
{
    const int LUHN[10] = {0, 5, 1, 6, 2, 7, 3, 8, 4, 9};
    const int m = n - 1;
    float cur[10];
    {
        const float* d = p + 10;
        bool perm = ((0 & 1) == (m & 1));
        #pragma unroll
        for (int j = 0; j < 10; j++) cur[j] = perm ? d[LUHN[j]] : d[j];
    }
    for (int i = 1; i < m; i++) {
        const float* d = p + (size_t)(i + 1) * 10;
        bool perm = ((i & 1) == (m & 1));
        float dd[10];
        #pragma unroll
        for (int j = 0; j < 10; j++) dd[j] = perm ? d[LUHN[j]] : d[j];
        float nxt[10];
        #pragma unroll
        for (int s = 0; s < 10; s++) nxt[s] = 0.0f;
        #pragma unroll
        for (int a = 0; a < 10; a++)
            #pragma unroll
            for (int q = 0; q < 10; q++)
                nxt[(a + q) % 10] = fmaf(cur[a], dd[q], nxt[(a + q) % 10]);
        #pragma unroll
        for (int s = 0; s < 10; s++) cur[s] = nxt[s];
    }
    float t10 = 0.0f;
    #pragma unroll
    for (int a = 1; a < 10; a++) t10 = fmaf(p[a], cur[10 - a], t10);
    return logf(t10);
}

__global__ void luhn_kernel(float* __restrict__ out, int B, int n)
{
    int b = blockIdx.x * blockDim.x + threadIdx.x;
    if (b >= B) return;
    const float* p = g_probs + (size_t)b * n * 10;
    if (n == 16) out[b] = luhn_eval<16>(p);
    else         out[b] = luhn_generic(p, n);
}

// ---------------------------------------------------------------------------
extern "C" void kernel_launch(void* const* d_in, const int* in_sizes, int n_in,
                              void* d_out, int out_size)
{
    const float* inputs = (const float*)d_in[0];
    const float* cw1    = (const float*)d_in[1];
    const float* cb1    = (const float*)d_in[2];
    const float* cw2    = (const float*)d_in[3];
    const float* cb2    = (const float*)d_in[4];
    const float* dw1    = (const float*)d_in[5];
    const float* db1    = (const float*)d_in[6];
    const float* dw2    = (const float*)d_in[7];
    const float* db2    = (const float*)d_in[8];
    const float* dw3    = (const float*)d_in[9];
    const float* db3    = (const float*)d_in[10];
    float* out = (float*)d_out;

    const int B = out_size;                      // 1024
    const int n = in_sizes[0] / (B * 784);       // 16
    const int nimg = B * n;

    const size_t smem_bytes = SMEM_FLOATS * sizeof(float);  // 229,136 B
    cudaFuncSetAttribute(cnn_kernel, cudaFuncAttributeMaxDynamicSharedMemorySize,
                         (int)smem_bytes);

    cnn_kernel<<<148, 512, smem_bytes>>>(inputs, cw1, cb1, cw2, cb2,
                                         dw1, db1, dw2, db2, dw3, db3, nimg);
    luhn_kernel<<<(B + 15) / 16, 16>>>(out, B, n);
}